// round 11
// baseline (speedup 1.0000x reference)
#include <cuda_runtime.h>
#include <cuda_bf16.h>
#include <cstdint>

#define N_BATCH 8
#define NN      2048
#define DF      128
#define NF      128
#define A_ELEMS (N_BATCH * NN * NN)   /* 33554432 */
#define H_OFF   A_ELEMS
#define ROWTILES 32

// ---------------- scratch (no allocations allowed) ----------------
__device__ float g_dpart[ROWTILES * N_BATCH * NN];
__device__ float g_dr[N_BATCH * NN];
__device__ float          g_Xs   [N_BATCH * NN * DF];  // dr[j]*X[j,:]  (f32, epilogue)
__device__ __nv_bfloat16  g_Xsh  [N_BATCH * NN * DF];  // hi part (B operand)
__device__ __nv_bfloat16  g_Xsl  [N_BATCH * NN * DF];  // lo part
__device__ __nv_bfloat16  g_Dhi  [N_BATCH * NN * DF];  // gemm1 result hi
__device__ __nv_bfloat16  g_Dlo  [N_BATCH * NN * DF];  // gemm1 result lo
__device__ __nv_bfloat16  g_Whi[DF * NF];
__device__ __nv_bfloat16  g_Wlo[DF * NF];

// ---------------- helpers ----------------
__device__ __forceinline__ uint32_t smem_u32(const void* p) {
    uint32_t a;
    asm("{ .reg .u64 t; cvta.to.shared.u64 t, %1; cvt.u32.u64 %0, t; }" : "=r"(a) : "l"(p));
    return a;
}
__device__ __forceinline__ uint32_t bf2_bits(__nv_bfloat162 h) {
    return *reinterpret_cast<uint32_t*>(&h);
}
__device__ __forceinline__ void split4(float4 v, uint2& whi, uint2& wlo) {
    __nv_bfloat162 h01 = __floats2bfloat162_rn(v.x, v.y);
    __nv_bfloat162 h23 = __floats2bfloat162_rn(v.z, v.w);
    float2 f01 = __bfloat1622float2(h01);
    float2 f23 = __bfloat1622float2(h23);
    __nv_bfloat162 l01 = __floats2bfloat162_rn(v.x - f01.x, v.y - f01.y);
    __nv_bfloat162 l23 = __floats2bfloat162_rn(v.z - f23.x, v.w - f23.y);
    whi.x = bf2_bits(h01); whi.y = bf2_bits(h23);
    wlo.x = bf2_bits(l01); wlo.y = bf2_bits(l23);
}

#define LDSM4(r, a)                                                          \
    asm volatile("ldmatrix.sync.aligned.m8n8.x4.shared.b16 {%0,%1,%2,%3}, [%4];" \
        : "=r"((r)[0]), "=r"((r)[1]), "=r"((r)[2]), "=r"((r)[3]) : "r"(a))
#define LDSM4T(r, a)                                                         \
    asm volatile("ldmatrix.sync.aligned.m8n8.x4.trans.shared.b16 {%0,%1,%2,%3}, [%4];" \
        : "=r"((r)[0]), "=r"((r)[1]), "=r"((r)[2]), "=r"((r)[3]) : "r"(a))
#define MMA16816(d, a, b0, b1)                                               \
    asm volatile("mma.sync.aligned.m16n8k16.row.col.f32.bf16.bf16.f32 "      \
        "{%0,%1,%2,%3},{%4,%5,%6,%7},{%8,%9},{%0,%1,%2,%3};"                 \
        : "+f"((d)[0]), "+f"((d)[1]), "+f"((d)[2]), "+f"((d)[3])             \
        : "r"((a)[0]), "r"((a)[1]), "r"((a)[2]), "r"((a)[3]), "r"(b0), "r"(b1))
#define CPA16(sa, gp)                                                        \
    asm volatile("cp.async.cg.shared.global [%0], [%1], 16;" :: "r"(sa), "l"(gp))
#define CP_COMMIT() asm volatile("cp.async.commit_group;" ::: "memory")
#define CP_WAIT2()  asm volatile("cp.async.wait_group 2;" ::: "memory")

// ============================================================================
// Kernel 1: copy A -> out AND per-block partial column sums (deterministic).
// ============================================================================
__global__ void __launch_bounds__(512) colsum_copy_kernel(
    const float* __restrict__ A, float* __restrict__ out)
{
    const int rt = blockIdx.x, b = blockIdx.y, t = threadIdx.x;
    const size_t base = (size_t)b * NN * NN + (size_t)rt * 64 * NN;
    const float4* A4 = (const float4*)(A + base);
    float4*       O4 = (float4*)(out + base);

    float4 acc = make_float4(0.f, 0.f, 0.f, 0.f);
#pragma unroll 8
    for (int r = 0; r < 64; r++) {
        float4 v = A4[r * (NN / 4) + t];
        O4[r * (NN / 4) + t] = v;
        acc.x += v.x; acc.y += v.y; acc.z += v.z; acc.w += v.w;
    }
    ((float4*)(g_dpart + (size_t)rt * (N_BATCH * NN) + (size_t)b * NN))[t] = acc;
}

// ============================================================================
// Kernel 2: dr = rsqrt(1 + colsum); Xs = dr[j]*X[j,:]  (f32 + bf16 hi/lo)
// ============================================================================
__global__ void __launch_bounds__(128) finalize_kernel(const float* __restrict__ X)
{
    const int col = blockIdx.x;
    const int t   = threadIdx.x;
    float s = 1.0f;
#pragma unroll
    for (int rt = 0; rt < ROWTILES; rt++)
        s += g_dpart[rt * (N_BATCH * NN) + col];
    s = rsqrtf(s);
    if (t == 0) g_dr[col] = s;
    float v = s * X[(size_t)col * DF + t];
    g_Xs[(size_t)col * DF + t] = v;
    __nv_bfloat16 hi = __float2bfloat16_rn(v);
    g_Xsh[(size_t)col * DF + t] = hi;
    g_Xsl[(size_t)col * DF + t] = __float2bfloat16_rn(v - __bfloat162float(hi));
}

// ============================================================================
// Kernel 2b: W -> bf16 hi/lo
// ============================================================================
__global__ void __launch_bounds__(256) convw_kernel(const float* __restrict__ W)
{
    int i = blockIdx.x * 256 + threadIdx.x;
    float v = W[i];
    __nv_bfloat16 hi = __float2bfloat16_rn(v);
    g_Whi[i] = hi;
    g_Wlo[i] = __float2bfloat16_rn(v - __bfloat162float(hi));
}

// ============================================================================
// Kernel 3: gemm1, split-bf16 3-MMA. Tile 128(M) x 128(N), K-chunk 32,
// 256 threads (8 warps, 4M x 2N -> warp 32x64), 1 CTA/SM, grid 128.
// 4-stage pipeline: B hi/lo via cp.async ring (wait_group 2);
// A via distance-2 register prefetch -> split4 -> STS ring.
// One __syncthreads per chunk.
// ============================================================================
#define BK      32
#define NCH     (NN / BK)                 /* 64 */
#define PA_B    80                        /* A tile row stride, bytes */
#define PB_B    272                       /* B tile row stride, bytes */
#define SZ_A    (128 * PA_B)              /* 10240 */
#define SZ_B    (BK * PB_B)               /* 8704  */
#define STG4    (2 * SZ_A + 2 * SZ_B)     /* Ahi,Alo,Bhi,Blo = 37888 */
#define SM1_TOT (4 * STG4)                /* 151552 */

__global__ void __launch_bounds__(256, 1) gemm1_mma_kernel(const float* __restrict__ A)
{
    extern __shared__ __align__(16) char sm[];

    const int t = threadIdx.x;
    const int lane = t & 31, wid = t >> 5;
    const int wm = wid & 3, wn = wid >> 2;      // warp tile: 32 M x 64 N
    const int b = blockIdx.y, i0 = blockIdx.x * 128;

    const float* Ab = A + (size_t)b * NN * NN + (size_t)i0 * NN;
    const __nv_bfloat16* Bhi = g_Xsh + (size_t)b * NN * DF;
    const __nv_bfloat16* Blo = g_Xsl + (size_t)b * NN * DF;

    const uint32_t sbase = smem_u32(sm);
    const int lrow  = lane & 15;
    const int lcol8 = (lane >> 4) * 8;

    // staging coords: A = 128 rows x 8 float4-cols = 1024 slots -> 4/thread
    // B = 32 rows x 16 16B-cols = 512 slots -> 2/thread (rows r0, r0+16)
    const int b_row0 = t >> 4, b_cc = t & 15;

    float acc[2][8][4];
#pragma unroll
    for (int mi = 0; mi < 2; mi++)
#pragma unroll
        for (int ni = 0; ni < 8; ni++)
#pragma unroll
            for (int q = 0; q < 4; q++) acc[mi][ni][q] = 0.f;

    // B issue helper (chunk -> slot chunk%4)
    auto issueB = [&](int c) {
        char* dst = sm + (c & 3) * STG4 + 2 * SZ_A;
        const size_t boff = (size_t)c * BK * DF;
#pragma unroll
        for (int i = 0; i < 2; i++) {
            int row = b_row0 + i * 16;
            CPA16(smem_u32(dst) + row * PB_B + b_cc * 16,
                  Bhi + boff + (size_t)row * DF + b_cc * 8);
            CPA16(smem_u32(dst) + SZ_B + row * PB_B + b_cc * 16,
                  Blo + boff + (size_t)row * DF + b_cc * 8);
        }
        CP_COMMIT();
    };
    auto ldgA = [&](int c, float4* r) {
#pragma unroll
        for (int i = 0; i < 4; i++) {
            int idx = t + i * 256, row = idx >> 3, c4 = idx & 7;
            r[i] = *(const float4*)(Ab + (size_t)row * NN + c * BK + c4 * 4);
        }
    };
    auto stsA = [&](int c, const float4* r) {
        char* dst = sm + (c & 3) * STG4;
#pragma unroll
        for (int i = 0; i < 4; i++) {
            int idx = t + i * 256, row = idx >> 3, c4 = idx & 7;
            uint2 whi, wlo; split4(r[i], whi, wlo);
            *(uint2*)(dst + row * PA_B + c4 * 8)        = whi;
            *(uint2*)(dst + SZ_A + row * PA_B + c4 * 8) = wlo;
        }
    };

    float4 ra[2][4];

    // ---- prologue: B stages 0..2 in flight; A chunk0 staged, chunk1 in regs
    issueB(0); issueB(1); issueB(2);
    ldgA(0, ra[0]);
    stsA(0, ra[0]);
    ldgA(1, ra[1]);

    for (int c = 0; c < NCH; c++) {
        CP_WAIT2();                 // B chunk c complete (<=2 younger pending)
        __syncthreads();            // cp.async + STS(c) visible to all warps

        if (c + 3 < NCH) issueB(c + 3);            // slot (c+3)%4 = (c-1)%4, free
        if (c + 2 < NCH) ldgA(c + 2, ra[c & 1]);   // dist-2 prefetch

        // ---- compute chunk c ----
        const uint32_t sAh = sbase + (c & 3) * STG4;
        const uint32_t sAl = sAh + SZ_A;
        const uint32_t sBh = sAh + 2 * SZ_A;
        const uint32_t sBl = sBh + SZ_B;
#pragma unroll
        for (int ks = 0; ks < 2; ks++) {
            uint32_t ah[2][4], al[2][4], bh[4][4], bl[4][4];
            const uint32_t arow = (wm * 32 + lrow) * PA_B + (ks * 16 + lcol8) * 2;
#pragma unroll
            for (int mi = 0; mi < 2; mi++) {
                LDSM4(ah[mi], sAh + arow + mi * 16 * PA_B);
                LDSM4(al[mi], sAl + arow + mi * 16 * PA_B);
            }
            const uint32_t brow = (ks * 16 + lrow) * PB_B + (wn * 64 + lcol8) * 2;
#pragma unroll
            for (int ni = 0; ni < 4; ni++) {
                LDSM4T(bh[ni], sBh + brow + ni * 32);
                LDSM4T(bl[ni], sBl + brow + ni * 32);
            }
#pragma unroll
            for (int mi = 0; mi < 2; mi++)
#pragma unroll
                for (int ni = 0; ni < 4; ni++) {
                    MMA16816(acc[mi][ni * 2],     ah[mi], bh[ni][0], bh[ni][1]);
                    MMA16816(acc[mi][ni * 2 + 1], ah[mi], bh[ni][2], bh[ni][3]);
                    MMA16816(acc[mi][ni * 2],     ah[mi], bl[ni][0], bl[ni][1]);
                    MMA16816(acc[mi][ni * 2 + 1], ah[mi], bl[ni][2], bl[ni][3]);
                    MMA16816(acc[mi][ni * 2],     al[mi], bh[ni][0], bh[ni][1]);
                    MMA16816(acc[mi][ni * 2 + 1], al[mi], bh[ni][2], bh[ni][3]);
                }
        }

        // ---- stage A chunk c+1 (loaded at iter c-1) into slot (c+1)%4 ----
        if (c + 1 < NCH) stsA(c + 1, ra[(c + 1) & 1]);
    }

    // ---- epilogue: v = dr[i]*(acc + Xs[i,:]) -> hi/lo bf16 pair ----
    const int g  = lane >> 2, tg = lane & 3;
#pragma unroll
    for (int mi = 0; mi < 2; mi++) {
#pragma unroll
        for (int rr = 0; rr < 2; rr++) {
            int r = i0 + wm * 32 + mi * 16 + g + rr * 8;
            float s = g_dr[b * NN + r];
            const float* Xrow = g_Xs + ((size_t)b * NN + r) * DF;
            __nv_bfloat162* DHrow = (__nv_bfloat162*)(g_Dhi + ((size_t)b * NN + r) * DF);
            __nv_bfloat162* DLrow = (__nv_bfloat162*)(g_Dlo + ((size_t)b * NN + r) * DF);
#pragma unroll
            for (int ni = 0; ni < 8; ni++) {
                int cb = wn * 64 + ni * 8 + tg * 2;
                float2 x = *(const float2*)(Xrow + cb);
                float v0 = s * (acc[mi][ni][rr * 2 + 0] + x.x);
                float v1 = s * (acc[mi][ni][rr * 2 + 1] + x.y);
                __nv_bfloat162 h = __floats2bfloat162_rn(v0, v1);
                float2 hf = __bfloat1622float2(h);
                DHrow[cb >> 1] = h;
                DLrow[cb >> 1] = __floats2bfloat162_rn(v0 - hf.x, v1 - hf.y);
            }
        }
    }
}

// ============================================================================
// Kernel 4: H = relu(DADH @ W), split-bf16 3-MMA, K=128 single stage.
// ============================================================================
#define G2_SZ   (128 * 272)                /* 34816 per tile */
#define SM2_TOT (4 * G2_SZ)                /* 139264 */

__global__ void __launch_bounds__(256) gemm2_mma_kernel(float* __restrict__ out)
{
    extern __shared__ __align__(16) char sm2[];

    const int t = threadIdx.x;
    const int lane = t & 31, wid = t >> 5;
    const int wm = wid & 3, wn = wid >> 2;
    const int i0 = blockIdx.x * 128;

    const uint32_t sbase = smem_u32(sm2);
    const int lrow  = lane & 15;
    const int lcol8 = (lane >> 4) * 8;

#pragma unroll
    for (int i = 0; i < 8; i++) {
        int idx = t + i * 256, row = idx >> 4, cc = idx & 15;
        size_t go = (size_t)(i0 + row) * DF + cc * 8;
        *(uint4*)(sm2 + row * 272 + cc * 16)          = *(const uint4*)(g_Dhi + go);
        *(uint4*)(sm2 + G2_SZ + row * 272 + cc * 16)  = *(const uint4*)(g_Dlo + go);
        size_t wo = (size_t)row * NF + cc * 8;
        *(uint4*)(sm2 + 2 * G2_SZ + row * 272 + cc * 16) = *(const uint4*)(g_Whi + wo);
        *(uint4*)(sm2 + 3 * G2_SZ + row * 272 + cc * 16) = *(const uint4*)(g_Wlo + wo);
    }
    __syncthreads();

    float acc[2][8][4];
#pragma unroll
    for (int mi = 0; mi < 2; mi++)
#pragma unroll
        for (int ni = 0; ni < 8; ni++)
#pragma unroll
            for (int q = 0; q < 4; q++) acc[mi][ni][q] = 0.f;

#pragma unroll
    for (int ks = 0; ks < 8; ks++) {
        uint32_t ah[2][4], al[2][4], bh[4][4], bl[4][4];
        const uint32_t arow = (wm * 32 + lrow) * 272 + (ks * 16 + lcol8) * 2;
#pragma unroll
        for (int mi = 0; mi < 2; mi++) {
            LDSM4(ah[mi], sbase + arow + mi * 16 * 272);
            LDSM4(al[mi], sbase + G2_SZ + arow + mi * 16 * 272);
        }
        const uint32_t brow = (ks * 16 + lrow) * 272 + (wn * 64 + lcol8) * 2;
#pragma unroll
        for (int ni = 0; ni < 4; ni++) {
            LDSM4T(bh[ni], sbase + 2 * G2_SZ + brow + ni * 32);
            LDSM4T(bl[ni], sbase + 3 * G2_SZ + brow + ni * 32);
        }
#pragma unroll
        for (int mi = 0; mi < 2; mi++)
#pragma unroll
            for (int ni = 0; ni < 4; ni++) {
                MMA16816(acc[mi][ni * 2],     ah[mi], bh[ni][0], bh[ni][1]);
                MMA16816(acc[mi][ni * 2 + 1], ah[mi], bh[ni][2], bh[ni][3]);
                MMA16816(acc[mi][ni * 2],     ah[mi], bl[ni][0], bl[ni][1]);
                MMA16816(acc[mi][ni * 2 + 1], ah[mi], bl[ni][2], bl[ni][3]);
                MMA16816(acc[mi][ni * 2],     al[mi], bh[ni][0], bh[ni][1]);
                MMA16816(acc[mi][ni * 2 + 1], al[mi], bh[ni][2], bh[ni][3]);
            }
    }

    const int g  = lane >> 2, tg = lane & 3;
#pragma unroll
    for (int mi = 0; mi < 2; mi++) {
#pragma unroll
        for (int rr = 0; rr < 2; rr++) {
            int r = i0 + wm * 32 + mi * 16 + g + rr * 8;
            float2* Orow = (float2*)(out + H_OFF + (size_t)r * NF);
#pragma unroll
            for (int ni = 0; ni < 8; ni++) {
                int cb = wn * 64 + ni * 8 + tg * 2;
                float2 o;
                o.x = fmaxf(acc[mi][ni][rr * 2 + 0], 0.f);
                o.y = fmaxf(acc[mi][ni][rr * 2 + 1], 0.f);
                Orow[cb >> 1] = o;
            }
        }
    }
}

// ============================================================================
extern "C" void kernel_launch(void* const* d_in, const int* in_sizes, int n_in,
                              void* d_out, int out_size)
{
    const float* A = (const float*)d_in[0];
    const float* X = (const float*)d_in[1];
    const float* W = (const float*)d_in[2];
    float* out = (float*)d_out;

    cudaFuncSetAttribute(gemm1_mma_kernel,
                         cudaFuncAttributeMaxDynamicSharedMemorySize, SM1_TOT);
    cudaFuncSetAttribute(gemm2_mma_kernel,
                         cudaFuncAttributeMaxDynamicSharedMemorySize, SM2_TOT);

    colsum_copy_kernel<<<dim3(ROWTILES, N_BATCH), 512>>>(A, out);
    finalize_kernel<<<N_BATCH * NN, 128>>>(X);
    convw_kernel<<<DF * NF / 256, 256>>>(W);
    gemm1_mma_kernel<<<dim3(NN / 128, N_BATCH), 256, SM1_TOT>>>(A);
    gemm2_mma_kernel<<<N_BATCH * NN / 128, 256, SM2_TOT>>>(out);
}

// round 13
// speedup vs baseline: 1.5208x; 1.5208x over previous
#include <cuda_runtime.h>
#include <cuda_bf16.h>
#include <cstdint>

#define N_BATCH 8
#define NN      2048
#define DF      128
#define NF      128
#define A_ELEMS (N_BATCH * NN * NN)   /* 33554432 */
#define H_OFF   A_ELEMS
#define ROWTILES 32

// ---------------- scratch (no allocations allowed) ----------------
__device__ float g_dpart[ROWTILES * N_BATCH * NN];
__device__ float g_dr[N_BATCH * NN];
__device__ float          g_Xs   [N_BATCH * NN * DF];  // dr[j]*X[j,:]  (f32, epilogue)
__device__ __nv_bfloat16  g_Xsh  [N_BATCH * NN * DF];  // hi part (B operand)
__device__ __nv_bfloat16  g_Xsl  [N_BATCH * NN * DF];  // lo part
__device__ __nv_bfloat16  g_Whi[DF * NF];
__device__ __nv_bfloat16  g_Wlo[DF * NF];

// ---------------- helpers ----------------
__device__ __forceinline__ uint32_t smem_u32(const void* p) {
    uint32_t a;
    asm("{ .reg .u64 t; cvta.to.shared.u64 t, %1; cvt.u32.u64 %0, t; }" : "=r"(a) : "l"(p));
    return a;
}
__device__ __forceinline__ uint32_t bf2_bits(__nv_bfloat162 h) {
    return *reinterpret_cast<uint32_t*>(&h);
}
__device__ __forceinline__ void split4(float4 v, uint2& whi, uint2& wlo) {
    __nv_bfloat162 h01 = __floats2bfloat162_rn(v.x, v.y);
    __nv_bfloat162 h23 = __floats2bfloat162_rn(v.z, v.w);
    float2 f01 = __bfloat1622float2(h01);
    float2 f23 = __bfloat1622float2(h23);
    __nv_bfloat162 l01 = __floats2bfloat162_rn(v.x - f01.x, v.y - f01.y);
    __nv_bfloat162 l23 = __floats2bfloat162_rn(v.z - f23.x, v.w - f23.y);
    whi.x = bf2_bits(h01); whi.y = bf2_bits(h23);
    wlo.x = bf2_bits(l01); wlo.y = bf2_bits(l23);
}

#define LDSM4(r, a)                                                          \
    asm volatile("ldmatrix.sync.aligned.m8n8.x4.shared.b16 {%0,%1,%2,%3}, [%4];" \
        : "=r"((r)[0]), "=r"((r)[1]), "=r"((r)[2]), "=r"((r)[3]) : "r"(a))
#define LDSM4T(r, a)                                                         \
    asm volatile("ldmatrix.sync.aligned.m8n8.x4.trans.shared.b16 {%0,%1,%2,%3}, [%4];" \
        : "=r"((r)[0]), "=r"((r)[1]), "=r"((r)[2]), "=r"((r)[3]) : "r"(a))
#define MMA16816(d, a, b0, b1)                                               \
    asm volatile("mma.sync.aligned.m16n8k16.row.col.f32.bf16.bf16.f32 "      \
        "{%0,%1,%2,%3},{%4,%5,%6,%7},{%8,%9},{%0,%1,%2,%3};"                 \
        : "+f"((d)[0]), "+f"((d)[1]), "+f"((d)[2]), "+f"((d)[3])             \
        : "r"((a)[0]), "r"((a)[1]), "r"((a)[2]), "r"((a)[3]), "r"(b0), "r"(b1))

// ============================================================================
// Kernel 1: copy A -> out AND per-block partial column sums (deterministic).
// ============================================================================
__global__ void __launch_bounds__(512) colsum_copy_kernel(
    const float* __restrict__ A, float* __restrict__ out)
{
    const int rt = blockIdx.x, b = blockIdx.y, t = threadIdx.x;
    const size_t base = (size_t)b * NN * NN + (size_t)rt * 64 * NN;
    const float4* A4 = (const float4*)(A + base);
    float4*       O4 = (float4*)(out + base);

    float4 acc = make_float4(0.f, 0.f, 0.f, 0.f);
#pragma unroll 8
    for (int r = 0; r < 64; r++) {
        float4 v = A4[r * (NN / 4) + t];
        O4[r * (NN / 4) + t] = v;
        acc.x += v.x; acc.y += v.y; acc.z += v.z; acc.w += v.w;
    }
    ((float4*)(g_dpart + (size_t)rt * (N_BATCH * NN) + (size_t)b * NN))[t] = acc;
}

// ============================================================================
// Kernel 2: dr = rsqrt(1 + colsum); Xs = dr[j]*X[j,:]  (f32 + bf16 hi/lo)
// ============================================================================
__global__ void __launch_bounds__(128) finalize_kernel(const float* __restrict__ X)
{
    const int col = blockIdx.x;
    const int t   = threadIdx.x;
    float s = 1.0f;
#pragma unroll
    for (int rt = 0; rt < ROWTILES; rt++)
        s += g_dpart[rt * (N_BATCH * NN) + col];
    s = rsqrtf(s);
    if (t == 0) g_dr[col] = s;
    float v = s * X[(size_t)col * DF + t];
    g_Xs[(size_t)col * DF + t] = v;
    __nv_bfloat16 hi = __float2bfloat16_rn(v);
    g_Xsh[(size_t)col * DF + t] = hi;
    g_Xsl[(size_t)col * DF + t] = __float2bfloat16_rn(v - __bfloat162float(hi));
}

// ============================================================================
// Kernel 2b: W -> bf16 hi/lo
// ============================================================================
__global__ void __launch_bounds__(256) convw_kernel(const float* __restrict__ W)
{
    int i = blockIdx.x * 256 + threadIdx.x;
    float v = W[i];
    __nv_bfloat16 hi = __float2bfloat16_rn(v);
    g_Whi[i] = hi;
    g_Wlo[i] = __float2bfloat16_rn(v - __bfloat162float(hi));
}

// ============================================================================
// Kernel 3: FUSED gemm1+gemm2, split-bf16 3-MMA.
// Mainloop: byte-exact R6 structure (tile 128x128, K-chunk 32, 256 threads,
// 8 warps 4M x 2N, 2-stage reg-staged double buffer) -> acc = A @ Xs.
// Epilogue: D = dr[i]*(acc + Xs[i,:]) split hi/lo -> SMEM (reusing stage bufs),
// then H = relu(D @ W) with W hi/lo preloaded in SMEM; H written to out.
// ============================================================================
#define BK      32
#define NCH     (NN / BK)                 /* 64 */
#define PA_B    80                        /* A tile row stride, bytes */
#define PB_B    272                       /* B tile row stride, bytes */
#define SZ_A    (128 * PA_B)              /* 10240 */
#define SZ_B    (BK * PB_B)               /* 8704  */
#define STG     (2 * SZ_A + 2 * SZ_B)     /* per-stage: Ahi,Alo,Bhi,Blo = 37888 */
#define SZ_D    (128 * 272)               /* 34816: D tile (reuses stage region) */
#define OFF_W   (2 * STG)                 /* 75776 */
#define SM1_TOT (2 * STG + 2 * SZ_D)      /* 145408 */

__global__ void __launch_bounds__(256) gemm_fused_kernel(const float* __restrict__ A,
                                                         float* __restrict__ out)
{
    extern __shared__ __align__(16) char sm[];

    const int t = threadIdx.x;
    const int lane = t & 31, wid = t >> 5;
    const int wm = wid & 3, wn = wid >> 2;      // warp tile: 32 M x 64 N
    const int b = blockIdx.y, i0 = blockIdx.x * 128;

    const float* Ab = A + (size_t)b * NN * NN + (size_t)i0 * NN;
    const __nv_bfloat16* Bhi = g_Xsh + (size_t)b * NN * DF;
    const __nv_bfloat16* Blo = g_Xsl + (size_t)b * NN * DF;

    const uint32_t sbase = smem_u32(sm);
    const int lrow  = lane & 15;
    const int lcol8 = (lane >> 4) * 8;

    float acc[2][8][4];
#pragma unroll
    for (int mi = 0; mi < 2; mi++)
#pragma unroll
        for (int ni = 0; ni < 8; ni++)
#pragma unroll
            for (int q = 0; q < 4; q++) acc[mi][ni][q] = 0.f;

    // ---- stage chunk 0 + W tiles ----
    {
#pragma unroll
        for (int i = 0; i < 4; i++) {
            int idx = t + i * 256, row = idx >> 3, c4 = idx & 7;
            float4 v = *(const float4*)(Ab + (size_t)row * NN + c4 * 4);
            uint2 whi, wlo; split4(v, whi, wlo);
            *(uint2*)(sm + row * PA_B + c4 * 8)        = whi;
            *(uint2*)(sm + SZ_A + row * PA_B + c4 * 8) = wlo;
        }
#pragma unroll
        for (int i = 0; i < 2; i++) {
            int idx = t + i * 256, row = idx >> 4, cc = idx & 15;
            *(uint4*)(sm + 2 * SZ_A + row * PB_B + cc * 16) =
                *(const uint4*)(Bhi + (size_t)row * DF + cc * 8);
            *(uint4*)(sm + 2 * SZ_A + SZ_B + row * PB_B + cc * 16) =
                *(const uint4*)(Blo + (size_t)row * DF + cc * 8);
        }
        // W hi/lo: 128 rows x 16 x 16B each
#pragma unroll
        for (int i = 0; i < 8; i++) {
            int idx = t + i * 256, row = idx >> 4, cc = idx & 15;
            size_t wo = (size_t)row * NF + cc * 8;
            *(uint4*)(sm + OFF_W + row * 272 + cc * 16)        = *(const uint4*)(g_Whi + wo);
            *(uint4*)(sm + OFF_W + SZ_D + row * 272 + cc * 16) = *(const uint4*)(g_Wlo + wo);
        }
    }
    __syncthreads();

    float4 ra[4];
    uint4  rbh[2], rbl[2];

    for (int c = 0; c < NCH; c++) {
        const int st = c & 1;
        if (c + 1 < NCH) {
            const float* Asrc = Ab + (c + 1) * BK;
#pragma unroll
            for (int i = 0; i < 4; i++) {
                int idx = t + i * 256, row = idx >> 3, c4 = idx & 7;
                ra[i] = *(const float4*)(Asrc + (size_t)row * NN + c4 * 4);
            }
            const size_t boff = (size_t)(c + 1) * BK * DF;
#pragma unroll
            for (int i = 0; i < 2; i++) {
                int idx = t + i * 256, row = idx >> 4, cc = idx & 15;
                rbh[i] = *(const uint4*)(Bhi + boff + (size_t)row * DF + cc * 8);
                rbl[i] = *(const uint4*)(Blo + boff + (size_t)row * DF + cc * 8);
            }
        }
        // ---- compute on stage st ----
        const uint32_t sAh = sbase + st * STG;
        const uint32_t sAl = sAh + SZ_A;
        const uint32_t sBh = sAh + 2 * SZ_A;
        const uint32_t sBl = sBh + SZ_B;
#pragma unroll
        for (int ks = 0; ks < 2; ks++) {
            uint32_t ah[2][4], al[2][4], bh[4][4], bl[4][4];
            const uint32_t arow = (wm * 32 + lrow) * PA_B + (ks * 16 + lcol8) * 2;
#pragma unroll
            for (int mi = 0; mi < 2; mi++) {
                LDSM4(ah[mi], sAh + arow + mi * 16 * PA_B);
                LDSM4(al[mi], sAl + arow + mi * 16 * PA_B);
            }
            const uint32_t brow = (ks * 16 + lrow) * PB_B + (wn * 64 + lcol8) * 2;
#pragma unroll
            for (int ni = 0; ni < 4; ni++) {
                LDSM4T(bh[ni], sBh + brow + ni * 32);
                LDSM4T(bl[ni], sBl + brow + ni * 32);
            }
#pragma unroll
            for (int mi = 0; mi < 2; mi++)
#pragma unroll
                for (int ni = 0; ni < 4; ni++) {
                    MMA16816(acc[mi][ni * 2],     ah[mi], bh[ni][0], bh[ni][1]);
                    MMA16816(acc[mi][ni * 2 + 1], ah[mi], bh[ni][2], bh[ni][3]);
                    MMA16816(acc[mi][ni * 2],     ah[mi], bl[ni][0], bl[ni][1]);
                    MMA16816(acc[mi][ni * 2 + 1], ah[mi], bl[ni][2], bl[ni][3]);
                    MMA16816(acc[mi][ni * 2],     al[mi], bh[ni][0], bh[ni][1]);
                    MMA16816(acc[mi][ni * 2 + 1], al[mi], bh[ni][2], bh[ni][3]);
                }
        }
        // ---- store staged chunk c+1 ----
        if (c + 1 < NCH) {
            const int ns = (c + 1) & 1;
            char* dst = sm + ns * STG;
#pragma unroll
            for (int i = 0; i < 4; i++) {
                int idx = t + i * 256, row = idx >> 3, c4 = idx & 7;
                uint2 whi, wlo; split4(ra[i], whi, wlo);
                *(uint2*)(dst + row * PA_B + c4 * 8)        = whi;
                *(uint2*)(dst + SZ_A + row * PA_B + c4 * 8) = wlo;
            }
#pragma unroll
            for (int i = 0; i < 2; i++) {
                int idx = t + i * 256, row = idx >> 4, cc = idx & 15;
                *(uint4*)(dst + 2 * SZ_A + row * PB_B + cc * 16)        = rbh[i];
                *(uint4*)(dst + 2 * SZ_A + SZ_B + row * PB_B + cc * 16) = rbl[i];
            }
        }
        __syncthreads();
    }

    // ---- epilogue A: D = dr[i]*(acc + Xs[i,:]) -> hi/lo bf16 into SMEM ----
    // D tiles reuse the (now dead) stage region: Dhi at 0, Dlo at SZ_D.
    const int g  = lane >> 2, tg = lane & 3;
#pragma unroll
    for (int mi = 0; mi < 2; mi++) {
#pragma unroll
        for (int rr = 0; rr < 2; rr++) {
            int rl = wm * 32 + mi * 16 + g + rr * 8;     // local row 0..127
            int r  = i0 + rl;
            float s = g_dr[b * NN + r];
            const float* Xrow = g_Xs + ((size_t)b * NN + r) * DF;
#pragma unroll
            for (int ni = 0; ni < 8; ni++) {
                int cb = wn * 64 + ni * 8 + tg * 2;
                float2 x = *(const float2*)(Xrow + cb);
                float v0 = s * (acc[mi][ni][rr * 2 + 0] + x.x);
                float v1 = s * (acc[mi][ni][rr * 2 + 1] + x.y);
                __nv_bfloat162 h = __floats2bfloat162_rn(v0, v1);
                float2 hf = __bfloat1622float2(h);
                __nv_bfloat162 l = __floats2bfloat162_rn(v0 - hf.x, v1 - hf.y);
                *(__nv_bfloat162*)(sm + rl * 272 + cb * 2)        = h;
                *(__nv_bfloat162*)(sm + SZ_D + rl * 272 + cb * 2) = l;
            }
        }
    }
    __syncthreads();

    // ---- epilogue B: H = relu(D @ W) (verified gemm2 body, K=128) ----
    float ac2[2][8][4];
#pragma unroll
    for (int mi = 0; mi < 2; mi++)
#pragma unroll
        for (int ni = 0; ni < 8; ni++)
#pragma unroll
            for (int q = 0; q < 4; q++) ac2[mi][ni][q] = 0.f;

#pragma unroll
    for (int ks = 0; ks < 8; ks++) {
        uint32_t ah[2][4], al[2][4], bh[4][4], bl[4][4];
        const uint32_t arow = (wm * 32 + lrow) * 272 + (ks * 16 + lcol8) * 2;
#pragma unroll
        for (int mi = 0; mi < 2; mi++) {
            LDSM4(ah[mi], sbase + arow + mi * 16 * 272);
            LDSM4(al[mi], sbase + SZ_D + arow + mi * 16 * 272);
        }
        const uint32_t brow = (ks * 16 + lrow) * 272 + (wn * 64 + lcol8) * 2;
#pragma unroll
        for (int ni = 0; ni < 4; ni++) {
            LDSM4T(bh[ni], sbase + OFF_W + brow + ni * 32);
            LDSM4T(bl[ni], sbase + OFF_W + SZ_D + brow + ni * 32);
        }
#pragma unroll
        for (int mi = 0; mi < 2; mi++)
#pragma unroll
            for (int ni = 0; ni < 4; ni++) {
                MMA16816(ac2[mi][ni * 2],     ah[mi], bh[ni][0], bh[ni][1]);
                MMA16816(ac2[mi][ni * 2 + 1], ah[mi], bh[ni][2], bh[ni][3]);
                MMA16816(ac2[mi][ni * 2],     ah[mi], bl[ni][0], bl[ni][1]);
                MMA16816(ac2[mi][ni * 2 + 1], ah[mi], bl[ni][2], bl[ni][3]);
                MMA16816(ac2[mi][ni * 2],     al[mi], bh[ni][0], bh[ni][1]);
                MMA16816(ac2[mi][ni * 2 + 1], al[mi], bh[ni][2], bh[ni][3]);
            }
    }

#pragma unroll
    for (int mi = 0; mi < 2; mi++) {
#pragma unroll
        for (int rr = 0; rr < 2; rr++) {
            int r = b * NN + i0 + wm * 32 + mi * 16 + g + rr * 8;
            float2* Orow = (float2*)(out + H_OFF + (size_t)r * NF);
#pragma unroll
            for (int ni = 0; ni < 8; ni++) {
                int cb = wn * 64 + ni * 8 + tg * 2;
                float2 o;
                o.x = fmaxf(ac2[mi][ni][rr * 2 + 0], 0.f);
                o.y = fmaxf(ac2[mi][ni][rr * 2 + 1], 0.f);
                Orow[cb >> 1] = o;
            }
        }
    }
}

// ============================================================================
extern "C" void kernel_launch(void* const* d_in, const int* in_sizes, int n_in,
                              void* d_out, int out_size)
{
    const float* A = (const float*)d_in[0];
    const float* X = (const float*)d_in[1];
    const float* W = (const float*)d_in[2];
    float* out = (float*)d_out;

    cudaFuncSetAttribute(gemm_fused_kernel,
                         cudaFuncAttributeMaxDynamicSharedMemorySize, SM1_TOT);

    colsum_copy_kernel<<<dim3(ROWTILES, N_BATCH), 512>>>(A, out);
    finalize_kernel<<<N_BATCH * NN, 128>>>(X);
    convw_kernel<<<DF * NF / 256, 256>>>(W);
    gemm_fused_kernel<<<dim3(NN / 128, N_BATCH), 256, SM1_TOT>>>(A, out);
}

// round 14
// speedup vs baseline: 1.5302x; 1.0061x over previous
#include <cuda_runtime.h>
#include <cuda_bf16.h>
#include <cstdint>

#define N_BATCH 8
#define NN      2048
#define DF      128
#define NF      128
#define A_ELEMS (N_BATCH * NN * NN)   /* 33554432 */
#define H_OFF   A_ELEMS
#define ROWTILES 32

// ---------------- scratch (no allocations allowed) ----------------
__device__ float g_dpart[ROWTILES * N_BATCH * NN];
__device__ float g_dr[N_BATCH * NN];
__device__ float          g_Xs   [N_BATCH * NN * DF];  // dr[j]*X[j,:]  (f32, epilogue)
__device__ __nv_bfloat16  g_Xsh  [N_BATCH * NN * DF];  // hi part (B operand)
__device__ __nv_bfloat16  g_Xsl  [N_BATCH * NN * DF];  // lo part
__device__ __nv_bfloat16  g_Whi[DF * NF];
__device__ __nv_bfloat16  g_Wlo[DF * NF];

// ---------------- helpers ----------------
__device__ __forceinline__ uint32_t smem_u32(const void* p) {
    uint32_t a;
    asm("{ .reg .u64 t; cvta.to.shared.u64 t, %1; cvt.u32.u64 %0, t; }" : "=r"(a) : "l"(p));
    return a;
}
__device__ __forceinline__ uint32_t bf2_bits(__nv_bfloat162 h) {
    return *reinterpret_cast<uint32_t*>(&h);
}
__device__ __forceinline__ void split4(float4 v, uint2& whi, uint2& wlo) {
    __nv_bfloat162 h01 = __floats2bfloat162_rn(v.x, v.y);
    __nv_bfloat162 h23 = __floats2bfloat162_rn(v.z, v.w);
    float2 f01 = __bfloat1622float2(h01);
    float2 f23 = __bfloat1622float2(h23);
    __nv_bfloat162 l01 = __floats2bfloat162_rn(v.x - f01.x, v.y - f01.y);
    __nv_bfloat162 l23 = __floats2bfloat162_rn(v.z - f23.x, v.w - f23.y);
    whi.x = bf2_bits(h01); whi.y = bf2_bits(h23);
    wlo.x = bf2_bits(l01); wlo.y = bf2_bits(l23);
}

#define LDSM4(r, a)                                                          \
    asm volatile("ldmatrix.sync.aligned.m8n8.x4.shared.b16 {%0,%1,%2,%3}, [%4];" \
        : "=r"((r)[0]), "=r"((r)[1]), "=r"((r)[2]), "=r"((r)[3]) : "r"(a))
#define LDSM4T(r, a)                                                         \
    asm volatile("ldmatrix.sync.aligned.m8n8.x4.trans.shared.b16 {%0,%1,%2,%3}, [%4];" \
        : "=r"((r)[0]), "=r"((r)[1]), "=r"((r)[2]), "=r"((r)[3]) : "r"(a))
#define MMA16816(d, a, b0, b1)                                               \
    asm volatile("mma.sync.aligned.m16n8k16.row.col.f32.bf16.bf16.f32 "      \
        "{%0,%1,%2,%3},{%4,%5,%6,%7},{%8,%9},{%0,%1,%2,%3};"                 \
        : "+f"((d)[0]), "+f"((d)[1]), "+f"((d)[2]), "+f"((d)[3])             \
        : "r"((a)[0]), "r"((a)[1]), "r"((a)[2]), "r"((a)[3]), "r"(b0), "r"(b1))

// ============================================================================
// Kernel 1: per-block partial column sums of A (read-only; copy moved to gemm).
// ============================================================================
__global__ void __launch_bounds__(512) colsum_kernel(const float* __restrict__ A)
{
    const int rt = blockIdx.x, b = blockIdx.y, t = threadIdx.x;
    const size_t base = (size_t)b * NN * NN + (size_t)rt * 64 * NN;
    const float4* A4 = (const float4*)(A + base);

    float4 acc = make_float4(0.f, 0.f, 0.f, 0.f);
#pragma unroll 8
    for (int r = 0; r < 64; r++) {
        float4 v = A4[r * (NN / 4) + t];
        acc.x += v.x; acc.y += v.y; acc.z += v.z; acc.w += v.w;
    }
    ((float4*)(g_dpart + (size_t)rt * (N_BATCH * NN) + (size_t)b * NN))[t] = acc;
}

// ============================================================================
// Kernel 2: dr = rsqrt(1 + colsum); Xs = dr[j]*X[j,:]  (f32 + bf16 hi/lo)
// ============================================================================
__global__ void __launch_bounds__(128) finalize_kernel(const float* __restrict__ X)
{
    const int col = blockIdx.x;
    const int t   = threadIdx.x;
    float s = 1.0f;
#pragma unroll
    for (int rt = 0; rt < ROWTILES; rt++)
        s += g_dpart[rt * (N_BATCH * NN) + col];
    s = rsqrtf(s);
    if (t == 0) g_dr[col] = s;
    float v = s * X[(size_t)col * DF + t];
    g_Xs[(size_t)col * DF + t] = v;
    __nv_bfloat16 hi = __float2bfloat16_rn(v);
    g_Xsh[(size_t)col * DF + t] = hi;
    g_Xsl[(size_t)col * DF + t] = __float2bfloat16_rn(v - __bfloat162float(hi));
}

// ============================================================================
// Kernel 2b: W -> bf16 hi/lo
// ============================================================================
__global__ void __launch_bounds__(256) convw_kernel(const float* __restrict__ W)
{
    int i = blockIdx.x * 256 + threadIdx.x;
    float v = W[i];
    __nv_bfloat16 hi = __float2bfloat16_rn(v);
    g_Whi[i] = hi;
    g_Wlo[i] = __float2bfloat16_rn(v - __bfloat162float(hi));
}

// ============================================================================
// Kernel 3: FUSED gemm1+gemm2, split-bf16 3-MMA.  (R12 structure, plus:
// each staged A chunk is also written to out -> the A copy piggybacks on
// the GEMM's one-and-only read of A.)
// ============================================================================
#define BK      32
#define NCH     (NN / BK)                 /* 64 */
#define PA_B    80                        /* A tile row stride, bytes */
#define PB_B    272                       /* B tile row stride, bytes */
#define SZ_A    (128 * PA_B)              /* 10240 */
#define SZ_B    (BK * PB_B)               /* 8704  */
#define STG     (2 * SZ_A + 2 * SZ_B)     /* per-stage: Ahi,Alo,Bhi,Blo = 37888 */
#define SZ_D    (128 * 272)               /* 34816: D tile (reuses stage region) */
#define OFF_W   (2 * STG)                 /* 75776 */
#define SM1_TOT (2 * STG + 2 * SZ_D)      /* 145408 */

__global__ void __launch_bounds__(256) gemm_fused_kernel(const float* __restrict__ A,
                                                         float* __restrict__ out)
{
    extern __shared__ __align__(16) char sm[];

    const int t = threadIdx.x;
    const int lane = t & 31, wid = t >> 5;
    const int wm = wid & 3, wn = wid >> 2;      // warp tile: 32 M x 64 N
    const int b = blockIdx.y, i0 = blockIdx.x * 128;

    const float* Ab = A   + (size_t)b * NN * NN + (size_t)i0 * NN;
    float*       Ob = out + (size_t)b * NN * NN + (size_t)i0 * NN;
    const __nv_bfloat16* Bhi = g_Xsh + (size_t)b * NN * DF;
    const __nv_bfloat16* Blo = g_Xsl + (size_t)b * NN * DF;

    const uint32_t sbase = smem_u32(sm);
    const int lrow  = lane & 15;
    const int lcol8 = (lane >> 4) * 8;

    float acc[2][8][4];
#pragma unroll
    for (int mi = 0; mi < 2; mi++)
#pragma unroll
        for (int ni = 0; ni < 8; ni++)
#pragma unroll
            for (int q = 0; q < 4; q++) acc[mi][ni][q] = 0.f;

    // ---- stage chunk 0 (also copy it to out) + W tiles ----
    {
#pragma unroll
        for (int i = 0; i < 4; i++) {
            int idx = t + i * 256, row = idx >> 3, c4 = idx & 7;
            float4 v = *(const float4*)(Ab + (size_t)row * NN + c4 * 4);
            *(float4*)(Ob + (size_t)row * NN + c4 * 4) = v;
            uint2 whi, wlo; split4(v, whi, wlo);
            *(uint2*)(sm + row * PA_B + c4 * 8)        = whi;
            *(uint2*)(sm + SZ_A + row * PA_B + c4 * 8) = wlo;
        }
#pragma unroll
        for (int i = 0; i < 2; i++) {
            int idx = t + i * 256, row = idx >> 4, cc = idx & 15;
            *(uint4*)(sm + 2 * SZ_A + row * PB_B + cc * 16) =
                *(const uint4*)(Bhi + (size_t)row * DF + cc * 8);
            *(uint4*)(sm + 2 * SZ_A + SZ_B + row * PB_B + cc * 16) =
                *(const uint4*)(Blo + (size_t)row * DF + cc * 8);
        }
        // W hi/lo: 128 rows x 16 x 16B each
#pragma unroll
        for (int i = 0; i < 8; i++) {
            int idx = t + i * 256, row = idx >> 4, cc = idx & 15;
            size_t wo = (size_t)row * NF + cc * 8;
            *(uint4*)(sm + OFF_W + row * 272 + cc * 16)        = *(const uint4*)(g_Whi + wo);
            *(uint4*)(sm + OFF_W + SZ_D + row * 272 + cc * 16) = *(const uint4*)(g_Wlo + wo);
        }
    }
    __syncthreads();

    float4 ra[4];
    uint4  rbh[2], rbl[2];

    for (int c = 0; c < NCH; c++) {
        const int st = c & 1;
        if (c + 1 < NCH) {
            const float* Asrc = Ab + (c + 1) * BK;
#pragma unroll
            for (int i = 0; i < 4; i++) {
                int idx = t + i * 256, row = idx >> 3, c4 = idx & 7;
                ra[i] = *(const float4*)(Asrc + (size_t)row * NN + c4 * 4);
            }
            const size_t boff = (size_t)(c + 1) * BK * DF;
#pragma unroll
            for (int i = 0; i < 2; i++) {
                int idx = t + i * 256, row = idx >> 4, cc = idx & 15;
                rbh[i] = *(const uint4*)(Bhi + boff + (size_t)row * DF + cc * 8);
                rbl[i] = *(const uint4*)(Blo + boff + (size_t)row * DF + cc * 8);
            }
        }
        // ---- compute on stage st ----
        const uint32_t sAh = sbase + st * STG;
        const uint32_t sAl = sAh + SZ_A;
        const uint32_t sBh = sAh + 2 * SZ_A;
        const uint32_t sBl = sBh + SZ_B;
#pragma unroll
        for (int ks = 0; ks < 2; ks++) {
            uint32_t ah[2][4], al[2][4], bh[4][4], bl[4][4];
            const uint32_t arow = (wm * 32 + lrow) * PA_B + (ks * 16 + lcol8) * 2;
#pragma unroll
            for (int mi = 0; mi < 2; mi++) {
                LDSM4(ah[mi], sAh + arow + mi * 16 * PA_B);
                LDSM4(al[mi], sAl + arow + mi * 16 * PA_B);
            }
            const uint32_t brow = (ks * 16 + lrow) * PB_B + (wn * 64 + lcol8) * 2;
#pragma unroll
            for (int ni = 0; ni < 4; ni++) {
                LDSM4T(bh[ni], sBh + brow + ni * 32);
                LDSM4T(bl[ni], sBl + brow + ni * 32);
            }
#pragma unroll
            for (int mi = 0; mi < 2; mi++)
#pragma unroll
                for (int ni = 0; ni < 4; ni++) {
                    MMA16816(acc[mi][ni * 2],     ah[mi], bh[ni][0], bh[ni][1]);
                    MMA16816(acc[mi][ni * 2 + 1], ah[mi], bh[ni][2], bh[ni][3]);
                    MMA16816(acc[mi][ni * 2],     ah[mi], bl[ni][0], bl[ni][1]);
                    MMA16816(acc[mi][ni * 2 + 1], ah[mi], bl[ni][2], bl[ni][3]);
                    MMA16816(acc[mi][ni * 2],     al[mi], bh[ni][0], bh[ni][1]);
                    MMA16816(acc[mi][ni * 2 + 1], al[mi], bh[ni][2], bh[ni][3]);
                }
        }
        // ---- store staged chunk c+1 (SMEM) and copy it to out ----
        if (c + 1 < NCH) {
            const int ns = (c + 1) & 1;
            char* dst = sm + ns * STG;
            float* Oc = Ob + (c + 1) * BK;
#pragma unroll
            for (int i = 0; i < 4; i++) {
                int idx = t + i * 256, row = idx >> 3, c4 = idx & 7;
                *(float4*)(Oc + (size_t)row * NN + c4 * 4) = ra[i];
                uint2 whi, wlo; split4(ra[i], whi, wlo);
                *(uint2*)(dst + row * PA_B + c4 * 8)        = whi;
                *(uint2*)(dst + SZ_A + row * PA_B + c4 * 8) = wlo;
            }
#pragma unroll
            for (int i = 0; i < 2; i++) {
                int idx = t + i * 256, row = idx >> 4, cc = idx & 15;
                *(uint4*)(dst + 2 * SZ_A + row * PB_B + cc * 16)        = rbh[i];
                *(uint4*)(dst + 2 * SZ_A + SZ_B + row * PB_B + cc * 16) = rbl[i];
            }
        }
        __syncthreads();
    }

    // ---- epilogue A: D = dr[i]*(acc + Xs[i,:]) -> hi/lo bf16 into SMEM ----
    const int g  = lane >> 2, tg = lane & 3;
#pragma unroll
    for (int mi = 0; mi < 2; mi++) {
#pragma unroll
        for (int rr = 0; rr < 2; rr++) {
            int rl = wm * 32 + mi * 16 + g + rr * 8;     // local row 0..127
            int r  = i0 + rl;
            float s = g_dr[b * NN + r];
            const float* Xrow = g_Xs + ((size_t)b * NN + r) * DF;
#pragma unroll
            for (int ni = 0; ni < 8; ni++) {
                int cb = wn * 64 + ni * 8 + tg * 2;
                float2 x = *(const float2*)(Xrow + cb);
                float v0 = s * (acc[mi][ni][rr * 2 + 0] + x.x);
                float v1 = s * (acc[mi][ni][rr * 2 + 1] + x.y);
                __nv_bfloat162 h = __floats2bfloat162_rn(v0, v1);
                float2 hf = __bfloat1622float2(h);
                __nv_bfloat162 l = __floats2bfloat162_rn(v0 - hf.x, v1 - hf.y);
                *(__nv_bfloat162*)(sm + rl * 272 + cb * 2)        = h;
                *(__nv_bfloat162*)(sm + SZ_D + rl * 272 + cb * 2) = l;
            }
        }
    }
    __syncthreads();

    // ---- epilogue B: H = relu(D @ W) (verified gemm2 body, K=128) ----
    float ac2[2][8][4];
#pragma unroll
    for (int mi = 0; mi < 2; mi++)
#pragma unroll
        for (int ni = 0; ni < 8; ni++)
#pragma unroll
            for (int q = 0; q < 4; q++) ac2[mi][ni][q] = 0.f;

#pragma unroll
    for (int ks = 0; ks < 8; ks++) {
        uint32_t ah[2][4], al[2][4], bh[4][4], bl[4][4];
        const uint32_t arow = (wm * 32 + lrow) * 272 + (ks * 16 + lcol8) * 2;
#pragma unroll
        for (int mi = 0; mi < 2; mi++) {
            LDSM4(ah[mi], sbase + arow + mi * 16 * 272);
            LDSM4(al[mi], sbase + SZ_D + arow + mi * 16 * 272);
        }
        const uint32_t brow = (ks * 16 + lrow) * 272 + (wn * 64 + lcol8) * 2;
#pragma unroll
        for (int ni = 0; ni < 4; ni++) {
            LDSM4T(bh[ni], sbase + OFF_W + brow + ni * 32);
            LDSM4T(bl[ni], sbase + OFF_W + SZ_D + brow + ni * 32);
        }
#pragma unroll
        for (int mi = 0; mi < 2; mi++)
#pragma unroll
            for (int ni = 0; ni < 4; ni++) {
                MMA16816(ac2[mi][ni * 2],     ah[mi], bh[ni][0], bh[ni][1]);
                MMA16816(ac2[mi][ni * 2 + 1], ah[mi], bh[ni][2], bh[ni][3]);
                MMA16816(ac2[mi][ni * 2],     ah[mi], bl[ni][0], bl[ni][1]);
                MMA16816(ac2[mi][ni * 2 + 1], ah[mi], bl[ni][2], bl[ni][3]);
                MMA16816(ac2[mi][ni * 2],     al[mi], bh[ni][0], bh[ni][1]);
                MMA16816(ac2[mi][ni * 2 + 1], al[mi], bh[ni][2], bh[ni][3]);
            }
    }

#pragma unroll
    for (int mi = 0; mi < 2; mi++) {
#pragma unroll
        for (int rr = 0; rr < 2; rr++) {
            int r = b * NN + i0 + wm * 32 + mi * 16 + g + rr * 8;
            float2* Orow = (float2*)(out + H_OFF + (size_t)r * NF);
#pragma unroll
            for (int ni = 0; ni < 8; ni++) {
                int cb = wn * 64 + ni * 8 + tg * 2;
                float2 o;
                o.x = fmaxf(ac2[mi][ni][rr * 2 + 0], 0.f);
                o.y = fmaxf(ac2[mi][ni][rr * 2 + 1], 0.f);
                Orow[cb >> 1] = o;
            }
        }
    }
}

// ============================================================================
extern "C" void kernel_launch(void* const* d_in, const int* in_sizes, int n_in,
                              void* d_out, int out_size)
{
    const float* A = (const float*)d_in[0];
    const float* X = (const float*)d_in[1];
    const float* W = (const float*)d_in[2];
    float* out = (float*)d_out;

    cudaFuncSetAttribute(gemm_fused_kernel,
                         cudaFuncAttributeMaxDynamicSharedMemorySize, SM1_TOT);

    colsum_kernel<<<dim3(ROWTILES, N_BATCH), 512>>>(A);
    finalize_kernel<<<N_BATCH * NN, 128>>>(X);
    convw_kernel<<<DF * NF / 256, 256>>>(W);
    gemm_fused_kernel<<<dim3(NN / 128, N_BATCH), 256, SM1_TOT>>>(A, out);
}